// round 4
// baseline (speedup 1.0000x reference)
#include <cuda_runtime.h>
#include <math.h>

#define HD   128
#define B_   128
#define NU_  32
#define NT_  64

// strides (padded, even for 8B-aligned row-pair loads)
#define S_HU 34    // user tiles: 32 rows
#define S_HA 66    // antenna tiles / scratch: 64 rows

// ---- shared memory layout (floats), feature-major activations A_T[k][m] ----
#define OF_W    0                         // 16384  staged 128x128 weight (row-major [k][n])
#define OF_HU0  (OF_W   + 16384)          // 34*128 = 4352
#define OF_HU1  (OF_HU0 + 4352)
#define OF_HA0  (OF_HU1 + 4352)          // 66*128 = 8448
#define OF_HA1  (OF_HA0 + 8448)
#define OF_T    (OF_HA1 + 8448)          // 8448 scratch (in-place capable)
#define OF_VEC  (OF_T   + 8448)
#define OF_VEC2 (OF_VEC + 128)
#define SM_FLOATS (OF_VEC2 + 128)
#define SM_BYTES  (SM_FLOATS * 4)        // 202,752 B

// packed f32x2 helpers
#define PACK2(d, s) asm("mov.b64 %0, {%1, %1};" : "=l"(d) : "f"(s))
#define FMA2(acc, a, b) \
    asm("fma.rn.f32x2 %0, %1, %2, %0;" : "+l"(acc) : "l"(a), "l"(b))
#define UNPK2(lo, hi, s) asm("mov.b64 {%0, %1}, %2;" : "=f"(lo), "=f"(hi) : "l"(s))

// stage a 128x128 fp32 weight from global (L2-resident) into smem
__device__ __forceinline__ void load_w(float* dst, const float* __restrict__ src, int tid)
{
    const float4* s4 = (const float4*)src;
    float4*       d4 = (float4*)dst;
    #pragma unroll
    for (int i = 0; i < 16; i++)
        d4[tid + i * 256] = __ldg(s4 + tid + i * 256);
}

// C_T[n][m] = relu(A_T^T @ W + bias)[m][n]   (all feature-major in smem)
// A_T stride AS, C_T stride CS. 256 threads. In-place safe (sync before store).
template<int M, int AS, int CS, bool ADDV>
__device__ __forceinline__ void gemm2(const float* __restrict__ sA,
                                      const float* __restrict__ sW,
                                      const float* __restrict__ gBias,
                                      float* __restrict__ sC,
                                      const float* __restrict__ sAdd,
                                      int tid)
{
    constexpr int RM = M / 8;      // rows per thread
    constexpr int JP = RM / 2;     // row-pairs per thread
    const int tx = tid & 31;
    const int ty = tid >> 5;
    const int n0 = tx * 4;
    const int m0 = ty * RM;

    unsigned long long acc[JP][4];
    #pragma unroll
    for (int j = 0; j < JP; j++)
        #pragma unroll
        for (int c = 0; c < 4; c++) acc[j][c] = 0ULL;

    #pragma unroll 4
    for (int k = 0; k < HD; k++) {
        const float4 wv = *(const float4*)&sW[k * HD + n0];
        unsigned long long w0, w1, w2, w3;
        PACK2(w0, wv.x); PACK2(w1, wv.y); PACK2(w2, wv.z); PACK2(w3, wv.w);
        const float* ap = &sA[k * AS + m0];
        #pragma unroll
        for (int j = 0; j < JP; j++) {
            const unsigned long long a2 =
                *(const unsigned long long*)(ap + 2 * j);   // broadcast LDS.64
            FMA2(acc[j][0], a2, w0);
            FMA2(acc[j][1], a2, w1);
            FMA2(acc[j][2], a2, w2);
            FMA2(acc[j][3], a2, w3);
        }
    }

    __syncthreads();   // all A reads done -> in-place C writes are safe

    const float4 bv = __ldg((const float4*)&gBias[n0]);
    float mvv[4] = {0.f, 0.f, 0.f, 0.f};
    if (ADDV) {
        mvv[0] = sAdd[n0]; mvv[1] = sAdd[n0 + 1];
        mvv[2] = sAdd[n0 + 2]; mvv[3] = sAdd[n0 + 3];
    }
    const float bb[4] = {bv.x, bv.y, bv.z, bv.w};

    #pragma unroll
    for (int j = 0; j < JP; j++) {
        #pragma unroll
        for (int c = 0; c < 4; c++) {
            float lo, hi;
            UNPK2(lo, hi, acc[j][c]);
            lo = fmaxf(lo + bb[c], 0.f);
            hi = fmaxf(hi + bb[c], 0.f);
            if (ADDV) { lo += mvv[c]; hi += mvv[c]; }
            unsigned long long o;
            asm("mov.b64 %0, {%1, %2};" : "=l"(o) : "f"(lo), "f"(hi));
            *(unsigned long long*)&sC[(size_t)(n0 + c) * CS + m0 + 2 * j] = o;
        }
    }
}

// sOut[f] = mean over m of X_T[f*S + m]   (threads 0..127)
template<int S>
__device__ __forceinline__ void mean_t(const float* __restrict__ sX, int n,
                                       float* __restrict__ sOut, int tid)
{
    if (tid < HD) {
        const float* p = sX + (size_t)tid * S;
        float s = 0.f;
        for (int i = 0; i < n; i++) s += p[i];
        sOut[tid] = s / (float)n;
    }
}

#define LAYER(M, AS, CS, ADDV, A, WG, BG, C, ADDP)                     \
    do {                                                               \
        __syncthreads();                                               \
        load_w(sW, (WG), tid);                                         \
        __syncthreads();                                               \
        gemm2<M, AS, CS, ADDV>((A), sW, (BG), (C), (ADDP), tid);       \
    } while (0)

__global__ __launch_bounds__(256, 1)
void gnn_fused(const float* __restrict__ uf,    const float* __restrict__ noise,
               const float* __restrict__ W_ue,  const float* __restrict__ b_ue,
               const float* __restrict__ W_t,   const float* __restrict__ b_t,
               const float* __restrict__ caWa,  const float* __restrict__ caba,
               const float* __restrict__ caWs,  const float* __restrict__ cabs,
               const float* __restrict__ caWc,  const float* __restrict__ cabc,
               const float* __restrict__ cuWa,  const float* __restrict__ cuba,
               const float* __restrict__ cuWs,  const float* __restrict__ cubs,
               const float* __restrict__ cuWc,  const float* __restrict__ cubc,
               const float* __restrict__ Wn,    const float* __restrict__ bn,
               float* __restrict__ out)
{
    extern __shared__ float sm[];
    float* sW    = sm + OF_W;
    float* sHU0  = sm + OF_HU0;
    float* sHU1  = sm + OF_HU1;
    float* sHA0  = sm + OF_HA0;
    float* sHA1  = sm + OF_HA1;
    float* sT    = sm + OF_T;
    float* sVec  = sm + OF_VEC;
    float* sVec2 = sm + OF_VEC2;

    const int b   = blockIdx.x;
    const int tid = threadIdx.x;
    const int WW  = HD * HD;

    // ---- stage user_feat transposed: sT[k][m] (stride S_HA) ----
    {
        const float* src = uf + (size_t)b * NU_ * HD;
        #pragma unroll
        for (int i = 0; i < NU_ * HD / 256; i++) {
            const int idx = tid + i * 256;
            const int m = idx >> 7;
            const int k = idx & (HD - 1);
            sT[(size_t)k * S_HA + m] = __ldg(&src[idx]);   // coalesced read
        }
    }
    load_w(sW, W_ue, tid);
    __syncthreads();
    gemm2<32, S_HA, S_HU, false>(sT, sW, b_ue, sHU0, nullptr, tid);

    // ---- ant = relu(mean_u(hu) @ W_t + b_t) ----
    __syncthreads();
    mean_t<S_HU>(sHU0, NU_, sVec, tid);
    load_w(sW, W_t, tid);
    __syncthreads();
    if (tid < HD) {
        float acc = __ldg(&b_t[tid]);
        #pragma unroll 8
        for (int k = 0; k < HD; k++) acc += sVec[k] * sW[k * HD + tid];
        sVec2[tid] = fmaxf(acc, 0.f);
    }
    __syncthreads();

    // ---- ha0_T[f][m] = ant[f] + noise[m][f] ----
    {
        const float* np_ = noise + (size_t)b * NT_ * HD;
        #pragma unroll
        for (int i = 0; i < NT_ * HD / 256; i++) {
            const int idx = tid + i * 256;
            const int m = idx >> 7;
            const int f = idx & (HD - 1);
            sHA0[(size_t)f * S_HA + m] = sVec2[f] + __ldg(&np_[idx]);
        }
    }

    float* hu_c = sHU0; float* hu_n = sHU1;
    float* ha_c = sHA0; float* ha_n = sHA1;

    #pragma unroll 1
    for (int r = 0; r < 2; r++) {
        // ---- na = comb( self(ha) + mean_b(aggr(hu)) ) ----
        LAYER(32, S_HU, S_HA, false, hu_c, caWa,      caba,      sT, nullptr);
        LAYER(32, S_HA, S_HA, false, sT,   caWa + WW, caba + HD, sT, nullptr);
        __syncthreads();
        mean_t<S_HA>(sT, NU_, sVec, tid);
        LAYER(64, S_HA, S_HA, false, ha_c, caWs,      cabs,      sT, nullptr);
        LAYER(64, S_HA, S_HA, true,  sT,   caWs + WW, cabs + HD, sT, sVec);
        LAYER(64, S_HA, S_HA, false, sT,   caWc,      cabc,      sT, nullptr);
        LAYER(64, S_HA, S_HA, false, sT,   caWc + WW, cabc + HD, ha_n, nullptr);

        // ---- nu = comb( self(hu) + mean_b(aggr(ha)) ) ----
        LAYER(64, S_HA, S_HA, false, ha_c, cuWa,      cuba,      sT, nullptr);
        LAYER(64, S_HA, S_HA, false, sT,   cuWa + WW, cuba + HD, sT, nullptr);
        __syncthreads();
        mean_t<S_HA>(sT, NT_, sVec, tid);
        LAYER(32, S_HU, S_HA, false, hu_c, cuWs,      cubs,      sT, nullptr);
        LAYER(32, S_HA, S_HA, true,  sT,   cuWs + WW, cubs + HD, sT, sVec);
        LAYER(32, S_HA, S_HA, false, sT,   cuWc,      cubc,      sT, nullptr);
        LAYER(32, S_HA, S_HU, false, sT,   cuWc + WW, cubc + HD, hu_n, nullptr);

        float* t;
        t = hu_c; hu_c = hu_n; hu_n = t;
        t = ha_c; ha_c = ha_n; ha_n = t;
    }

    // ---- final projection + complex-pair normalization ----
    __syncthreads();
    for (int i = tid; i < 512; i += 256)            // stage W_norm [128,16]
        ((float4*)sW)[i] = __ldg(((const float4*)Wn) + i);
    __syncthreads();

    const int c  = tid & 15;
    const int rb = tid >> 4;
    float yv[4];
    #pragma unroll
    for (int i = 0; i < 4; i++) {
        const int r = rb + 16 * i;
        float acc = __ldg(&bn[c]);
        #pragma unroll 8
        for (int k = 0; k < HD; k++)
            acc += ha_c[(size_t)k * S_HA + r] * sW[k * 16 + c];
        sT[r * 16 + c] = acc;
        yv[i] = acc;
    }
    __syncthreads();
    #pragma unroll
    for (int i = 0; i < 4; i++) {
        const int r  = rb + 16 * i;
        const int cp = c & 7;
        const float re  = sT[r * 16 + cp];
        const float im  = sT[r * 16 + cp + 8];
        const float mag = sqrtf(re * re + im * im);
        out[((size_t)b * NT_ + r) * 16 + c] = yv[i] / mag;
    }
}

// ---------------------------------------------------------------------
extern "C" void kernel_launch(void* const* d_in, const int* in_sizes, int n_in,
                              void* d_out, int out_size)
{
    (void)in_sizes; (void)n_in; (void)out_size;

    const float* user_feat = (const float*)d_in[0];
    const float* ant_noise = (const float*)d_in[1];
    // d_in[2..5]: edge indices — deterministic full bipartite per batch; unused.
    const float* W_ue = (const float*)d_in[6];
    const float* b_ue = (const float*)d_in[7];
    const float* W_t  = (const float*)d_in[8];
    const float* b_t  = (const float*)d_in[9];
    const float* caWa = (const float*)d_in[10];
    const float* caba = (const float*)d_in[11];
    const float* caWs = (const float*)d_in[12];
    const float* cabs = (const float*)d_in[13];
    const float* caWc = (const float*)d_in[14];
    const float* cabc = (const float*)d_in[15];
    const float* cuWa = (const float*)d_in[16];
    const float* cuba = (const float*)d_in[17];
    const float* cuWs = (const float*)d_in[18];
    const float* cubs = (const float*)d_in[19];
    const float* cuWc = (const float*)d_in[20];
    const float* cubc = (const float*)d_in[21];
    const float* Wn   = (const float*)d_in[22];
    const float* bn   = (const float*)d_in[23];
    float* out = (float*)d_out;

    static int smem_set = 0;
    if (!smem_set) {
        cudaFuncSetAttribute(gnn_fused,
                             cudaFuncAttributeMaxDynamicSharedMemorySize,
                             SM_BYTES);
        smem_set = 1;
    }

    gnn_fused<<<B_, 256, SM_BYTES>>>(
        user_feat, ant_noise,
        W_ue, b_ue, W_t, b_t,
        caWa, caba, caWs, cabs, caWc, cabc,
        cuWa, cuba, cuWs, cubs, cuWc, cubc,
        Wn, bn, out);
}

// round 5
// speedup vs baseline: 1.5568x; 1.5568x over previous
#include <cuda_runtime.h>
#include <math.h>

#define HD   128
#define B_   128
#define NU_  32
#define NT_  64

// strides (padded, even for 8B-aligned row-pair loads)
#define S_HU 34    // user tiles: 32 rows
#define S_HA 66    // antenna tiles / scratch: 64 rows

// ---- shared memory layout (floats), feature-major activations A_T[k][m] ----
#define OF_W    0                         // 16384  staged 128x128 weight (row-major [k][n])
#define OF_HU0  (OF_W   + 16384)          // 34*128 = 4352
#define OF_HU1  (OF_HU0 + 4352)
#define OF_HA0  (OF_HU1 + 4352)          // 66*128 = 8448
#define OF_HA1  (OF_HA0 + 8448)
#define OF_T    (OF_HA1 + 8448)          // 8448 scratch (in-place capable)
#define OF_VEC  (OF_T   + 8448)
#define OF_VEC2 (OF_VEC + 128)
#define SM_FLOATS (OF_VEC2 + 128)
#define SM_BYTES  (SM_FLOATS * 4)        // 202,752 B

// packed f32x2 helpers
#define PACK2(d, s) asm("mov.b64 %0, {%1, %1};" : "=l"(d) : "f"(s))
#define FMA2(acc, a, b) \
    asm("fma.rn.f32x2 %0, %1, %2, %0;" : "+l"(acc) : "l"(a), "l"(b))
#define UNPK2(lo, hi, s) asm("mov.b64 {%0, %1}, %2;" : "=f"(lo), "=f"(hi) : "l"(s))

// stage a 128x128 fp32 weight from global (L2-resident) into smem
__device__ __forceinline__ void load_w(float* dst, const float* __restrict__ src, int tid)
{
    const float4* s4 = (const float4*)src;
    float4*       d4 = (float4*)dst;
    #pragma unroll
    for (int i = 0; i < 16; i++)
        d4[tid + i * 256] = __ldg(s4 + tid + i * 256);
}

// C_T[n][m] = relu(A_T^T @ W + bias)[m][n]   (all feature-major in smem)
// A_T stride AS, C_T stride CS. 256 threads. In-place safe (sync before store).
template<int M, int AS, int CS, bool ADDV>
__device__ __forceinline__ void gemm2(const float* __restrict__ sA,
                                      const float* __restrict__ sW,
                                      const float* __restrict__ gBias,
                                      float* __restrict__ sC,
                                      const float* __restrict__ sAdd,
                                      int tid)
{
    constexpr int RM = M / 8;      // rows per thread
    constexpr int JP = RM / 2;     // row-pairs per thread
    const int tx = tid & 31;
    const int ty = tid >> 5;
    const int n0 = tx * 4;
    const int m0 = ty * RM;

    unsigned long long acc[JP][4];
    #pragma unroll
    for (int j = 0; j < JP; j++)
        #pragma unroll
        for (int c = 0; c < 4; c++) acc[j][c] = 0ULL;

    #pragma unroll 4
    for (int k = 0; k < HD; k++) {
        const float4 wv = *(const float4*)&sW[k * HD + n0];
        unsigned long long w0, w1, w2, w3;
        PACK2(w0, wv.x); PACK2(w1, wv.y); PACK2(w2, wv.z); PACK2(w3, wv.w);
        const float* ap = &sA[k * AS + m0];
        #pragma unroll
        for (int j = 0; j < JP; j++) {
            const unsigned long long a2 =
                *(const unsigned long long*)(ap + 2 * j);   // broadcast LDS.64
            FMA2(acc[j][0], a2, w0);
            FMA2(acc[j][1], a2, w1);
            FMA2(acc[j][2], a2, w2);
            FMA2(acc[j][3], a2, w3);
        }
    }

    __syncthreads();   // all A reads done -> in-place C writes are safe

    const float4 bv = __ldg((const float4*)&gBias[n0]);
    float mvv[4] = {0.f, 0.f, 0.f, 0.f};
    if (ADDV) {
        mvv[0] = sAdd[n0]; mvv[1] = sAdd[n0 + 1];
        mvv[2] = sAdd[n0 + 2]; mvv[3] = sAdd[n0 + 3];
    }
    const float bb[4] = {bv.x, bv.y, bv.z, bv.w};

    #pragma unroll
    for (int j = 0; j < JP; j++) {
        #pragma unroll
        for (int c = 0; c < 4; c++) {
            float lo, hi;
            UNPK2(lo, hi, acc[j][c]);
            lo = fmaxf(lo + bb[c], 0.f);
            hi = fmaxf(hi + bb[c], 0.f);
            if (ADDV) { lo += mvv[c]; hi += mvv[c]; }
            unsigned long long o;
            asm("mov.b64 %0, {%1, %2};" : "=l"(o) : "f"(lo), "f"(hi));
            *(unsigned long long*)&sC[(size_t)(n0 + c) * CS + m0 + 2 * j] = o;
        }
    }
}

// sOut[f] = mean over m of X_T[f*S + m]   (threads 0..127)
template<int S>
__device__ __forceinline__ void mean_t(const float* __restrict__ sX, int n,
                                       float* __restrict__ sOut, int tid)
{
    if (tid < HD) {
        const float* p = sX + (size_t)tid * S;
        float s = 0.f;
        for (int i = 0; i < n; i++) s += p[i];
        sOut[tid] = s / (float)n;
    }
}

#define LAYER(M, AS, CS, ADDV, A, WG, BG, C, ADDP)                     \
    do {                                                               \
        __syncthreads();                                               \
        load_w(sW, (WG), tid);                                         \
        __syncthreads();                                               \
        gemm2<M, AS, CS, ADDV>((A), sW, (BG), (C), (ADDP), tid);       \
    } while (0)

__global__ __launch_bounds__(256, 1)
void gnn_fused(const float* __restrict__ uf,    const float* __restrict__ noise,
               const float* __restrict__ W_ue,  const float* __restrict__ b_ue,
               const float* __restrict__ W_t,   const float* __restrict__ b_t,
               const float* __restrict__ caWa,  const float* __restrict__ caba,
               const float* __restrict__ caWs,  const float* __restrict__ cabs,
               const float* __restrict__ caWc,  const float* __restrict__ cabc,
               const float* __restrict__ cuWa,  const float* __restrict__ cuba,
               const float* __restrict__ cuWs,  const float* __restrict__ cubs,
               const float* __restrict__ cuWc,  const float* __restrict__ cubc,
               const float* __restrict__ Wn,    const float* __restrict__ bn,
               float* __restrict__ out)
{
    extern __shared__ float sm[];
    float* sW    = sm + OF_W;
    float* sHU0  = sm + OF_HU0;
    float* sHU1  = sm + OF_HU1;
    float* sHA0  = sm + OF_HA0;
    float* sHA1  = sm + OF_HA1;
    float* sT    = sm + OF_T;
    float* sVec  = sm + OF_VEC;
    float* sVec2 = sm + OF_VEC2;

    const int b   = blockIdx.x;
    const int tid = threadIdx.x;
    const int WW  = HD * HD;

    // ---- stage user_feat transposed: sT[k][m] (stride S_HA) ----
    {
        const float* src = uf + (size_t)b * NU_ * HD;
        #pragma unroll
        for (int i = 0; i < NU_ * HD / 256; i++) {
            const int idx = tid + i * 256;
            const int m = idx >> 7;
            const int k = idx & (HD - 1);
            sT[(size_t)k * S_HA + m] = __ldg(&src[idx]);   // coalesced read
        }
    }
    load_w(sW, W_ue, tid);
    __syncthreads();
    gemm2<32, S_HA, S_HU, false>(sT, sW, b_ue, sHU0, nullptr, tid);

    // ---- ant = relu(mean_u(hu) @ W_t + b_t) ----
    __syncthreads();
    mean_t<S_HU>(sHU0, NU_, sVec, tid);
    load_w(sW, W_t, tid);
    __syncthreads();
    if (tid < HD) {
        float acc = __ldg(&b_t[tid]);
        #pragma unroll 8
        for (int k = 0; k < HD; k++) acc += sVec[k] * sW[k * HD + tid];
        sVec2[tid] = fmaxf(acc, 0.f);
    }
    __syncthreads();

    // ---- ha0_T[f][m] = ant[f] + noise[m][f] ----
    {
        const float* np_ = noise + (size_t)b * NT_ * HD;
        #pragma unroll
        for (int i = 0; i < NT_ * HD / 256; i++) {
            const int idx = tid + i * 256;
            const int m = idx >> 7;
            const int f = idx & (HD - 1);
            sHA0[(size_t)f * S_HA + m] = sVec2[f] + __ldg(&np_[idx]);
        }
    }

    float* hu_c = sHU0; float* hu_n = sHU1;
    float* ha_c = sHA0; float* ha_n = sHA1;

    #pragma unroll 1
    for (int r = 0; r < 2; r++) {
        // ---- na = comb( self(ha) + mean_b(aggr(hu)) ) ----
        LAYER(32, S_HU, S_HA, false, hu_c, caWa,      caba,      sT, nullptr);
        LAYER(32, S_HA, S_HA, false, sT,   caWa + WW, caba + HD, sT, nullptr);
        __syncthreads();
        mean_t<S_HA>(sT, NU_, sVec, tid);
        LAYER(64, S_HA, S_HA, false, ha_c, caWs,      cabs,      sT, nullptr);
        LAYER(64, S_HA, S_HA, true,  sT,   caWs + WW, cabs + HD, sT, sVec);
        LAYER(64, S_HA, S_HA, false, sT,   caWc,      cabc,      sT, nullptr);
        LAYER(64, S_HA, S_HA, false, sT,   caWc + WW, cabc + HD, ha_n, nullptr);

        // ---- nu = comb( self(hu) + mean_b(aggr(ha)) ) ----
        LAYER(64, S_HA, S_HA, false, ha_c, cuWa,      cuba,      sT, nullptr);
        LAYER(64, S_HA, S_HA, false, sT,   cuWa + WW, cuba + HD, sT, nullptr);
        __syncthreads();
        mean_t<S_HA>(sT, NT_, sVec, tid);
        LAYER(32, S_HU, S_HA, false, hu_c, cuWs,      cubs,      sT, nullptr);
        LAYER(32, S_HA, S_HA, true,  sT,   cuWs + WW, cubs + HD, sT, sVec);
        LAYER(32, S_HA, S_HA, false, sT,   cuWc,      cubc,      sT, nullptr);
        LAYER(32, S_HA, S_HU, false, sT,   cuWc + WW, cubc + HD, hu_n, nullptr);

        float* t;
        t = hu_c; hu_c = hu_n; hu_n = t;
        t = ha_c; ha_c = ha_n; ha_n = t;
    }

    // ---- final projection + complex-pair normalization ----
    __syncthreads();
    for (int i = tid; i < 512; i += 256)            // stage W_norm [128,16]
        ((float4*)sW)[i] = __ldg(((const float4*)Wn) + i);
    __syncthreads();

    const int c  = tid & 15;
    const int rb = tid >> 4;
    float yv[4];
    #pragma unroll
    for (int i = 0; i < 4; i++) {
        const int r = rb + 16 * i;
        float acc = __ldg(&bn[c]);
        #pragma unroll 8
        for (int k = 0; k < HD; k++)
            acc += ha_c[(size_t)k * S_HA + r] * sW[k * 16 + c];
        sT[r * 16 + c] = acc;
        yv[i] = acc;
    }
    __syncthreads();
    #pragma unroll
    for (int i = 0; i < 4; i++) {
        const int r  = rb + 16 * i;
        const int cp = c & 7;
        const float re  = sT[r * 16 + cp];
        const float im  = sT[r * 16 + cp + 8];
        const float mag = sqrtf(re * re + im * im);
        out[((size_t)b * NT_ + r) * 16 + c] = yv[i] / mag;
    }
}

// ---------------------------------------------------------------------
extern "C" void kernel_launch(void* const* d_in, const int* in_sizes, int n_in,
                              void* d_out, int out_size)
{
    (void)in_sizes; (void)n_in; (void)out_size;

    const float* user_feat = (const float*)d_in[0];
    const float* ant_noise = (const float*)d_in[1];
    // d_in[2..5]: edge indices — deterministic full bipartite per batch; unused.
    const float* W_ue = (const float*)d_in[6];
    const float* b_ue = (const float*)d_in[7];
    const float* W_t  = (const float*)d_in[8];
    const float* b_t  = (const float*)d_in[9];
    const float* caWa = (const float*)d_in[10];
    const float* caba = (const float*)d_in[11];
    const float* caWs = (const float*)d_in[12];
    const float* cabs = (const float*)d_in[13];
    const float* caWc = (const float*)d_in[14];
    const float* cabc = (const float*)d_in[15];
    const float* cuWa = (const float*)d_in[16];
    const float* cuba = (const float*)d_in[17];
    const float* cuWs = (const float*)d_in[18];
    const float* cubs = (const float*)d_in[19];
    const float* cuWc = (const float*)d_in[20];
    const float* cubc = (const float*)d_in[21];
    const float* Wn   = (const float*)d_in[22];
    const float* bn   = (const float*)d_in[23];
    float* out = (float*)d_out;

    static int smem_set = 0;
    if (!smem_set) {
        cudaFuncSetAttribute(gnn_fused,
                             cudaFuncAttributeMaxDynamicSharedMemorySize,
                             SM_BYTES);
        smem_set = 1;
    }

    gnn_fused<<<B_, 256, SM_BYTES>>>(
        user_feat, ant_noise,
        W_ue, b_ue, W_t, b_t,
        caWa, caba, caWs, cabs, caWc, cabc,
        cuWa, cuba, cuWs, cubs, cuWc, cubc,
        Wn, bn, out);
}

// round 8
// speedup vs baseline: 2.8491x; 1.8301x over previous
#include <cuda_runtime.h>
#include <cuda_bf16.h>
#include <math.h>
#include <stdint.h>

#define HD  128
#define B_  128
#define NU_ 32
#define NT_ 64
#define P   272          // tile pitch bytes (136 bf16): 17*16B -> conflict-free ldmatrix
#define PE  136

// ---------------- packed weights in static global scratch ----------------
// 13 matrices, each: [k][n] bf16, hi plane then lo plane, pitch 136 elems.
__device__ __align__(16) __nv_bfloat16 g_w[13][2][HD * PE];

// ---------------- smem layout (byte offsets, all 16B aligned) ----------------
#define WPLANE   34816                    // 128*272
#define OFF_W0   0                        // 69632 (hi|lo)
#define OFF_W1   69632                    // 69632
#define OFF_TC   139264                   // 64-row tile: hi, lo
#define OFF_TC_L 156672                   // +64*272
#define OFF_TA   174080
#define OFF_TA_L 191488
#define OFF_TU   208896                   // 32-row tile
#define OFF_TU_L 217600                   // +32*272
#define OFF_VA   226304                   // 128 fp32
#define OFF_VU   226816
#define OFF_ANT  227328
#define SM_BYTES 227840

// ---------------- PTX helpers (all baseline sm_80+, no tcgen05) ----------------
__device__ __forceinline__ uint32_t smem_u32(const void* p) {
    uint32_t a;
    asm("{ .reg .u64 t; cvta.to.shared.u64 t, %1; cvt.u32.u64 %0, t; }"
        : "=r"(a) : "l"(p));
    return a;
}

#define LDSM4(d0, d1, d2, d3, a) \
    asm volatile("ldmatrix.sync.aligned.m8n8.x4.shared.b16 {%0,%1,%2,%3}, [%4];" \
                 : "=r"(d0), "=r"(d1), "=r"(d2), "=r"(d3) : "r"(a))
#define LDSM4T(d0, d1, d2, d3, a) \
    asm volatile("ldmatrix.sync.aligned.m8n8.x4.trans.shared.b16 {%0,%1,%2,%3}, [%4];" \
                 : "=r"(d0), "=r"(d1), "=r"(d2), "=r"(d3) : "r"(a))

#define MMA16816(c, a0, a1, a2, a3, b0, b1) \
    asm volatile("mma.sync.aligned.m16n8k16.row.col.f32.bf16.bf16.f32 " \
                 "{%0,%1,%2,%3}, {%4,%5,%6,%7}, {%8,%9}, {%0,%1,%2,%3};" \
                 : "+f"((c)[0]), "+f"((c)[1]), "+f"((c)[2]), "+f"((c)[3]) \
                 : "r"(a0), "r"(a1), "r"(a2), "r"(a3), "r"(b0), "r"(b1))

#define CP16(s, g) \
    asm volatile("cp.async.cg.shared.global [%0], [%1], 16;" :: "r"(s), "l"(g))
#define CP_COMMIT() asm volatile("cp.async.commit_group;" ::: "memory")
#define CP_WAIT1()  asm volatile("cp.async.wait_group 1;" ::: "memory")

__device__ __forceinline__ float bget(const char* p) {
    return __bfloat162float(*(const __nv_bfloat16*)p);
}

// ---------------- weight prep kernel: fp32 W[k][n] -> padded bf16 hi/lo ----------------
__global__ __launch_bounds__(256) void prep_w(
    const float* __restrict__ ue,
    const float* __restrict__ caWa, const float* __restrict__ caWs,
    const float* __restrict__ caWc, const float* __restrict__ cuWa,
    const float* __restrict__ cuWs, const float* __restrict__ cuWc)
{
    const float* srcs[13] = {
        ue,
        caWa, caWa + 16384, caWs, caWs + 16384, caWc, caWc + 16384,
        cuWa, cuWa + 16384, cuWs, cuWs + 16384, cuWc, cuWc + 16384
    };
    const int w = blockIdx.x;
    const float* src = srcs[w];
    __nv_bfloat16* hi = &g_w[w][0][0];
    __nv_bfloat16* lo = &g_w[w][1][0];
    for (int idx = threadIdx.x; idx < HD * PE; idx += 256) {
        const int k = idx / PE;
        const int n = idx - k * PE;
        float v = (n < HD) ? __ldg(src + k * HD + n) : 0.f;
        const __nv_bfloat16 h = __float2bfloat16(v);
        hi[idx] = h;
        lo[idx] = __float2bfloat16(v - __bfloat162float(h));
    }
}

// ---------------- one layer: C = relu(A@W + b)(+addv), split-bf16, 3 passes ----------------
// NNT = n-tiles (8 cols each) per warp: 8 for M=64 layers, 4 for M=32.
template<int NNT>
__device__ __forceinline__ void do_layer(
    uint32_t aHi, uint32_t aLo, uint32_t wHi, uint32_t wLo,
    char* outHi, char* outLo,
    const float* __restrict__ bias, const float* addv, int tid)
{
    const int lane = tid & 31;
    const int wp   = tid >> 5;
    int mt, nb;
    if (NNT == 8) { mt = (wp >> 1) * 16; nb = (wp & 1) * 64; }
    else          { mt = (wp >> 2) * 16; nb = (wp & 3) * 32; }

    float acc[NNT][4];
    #pragma unroll
    for (int t = 0; t < NNT; t++)
        #pragma unroll
        for (int c = 0; c < 4; c++) acc[t][c] = 0.f;

    const int r8  = (lane & 7) + ((lane >> 3) & 1) * 8;
    const int g16 = lane >> 4;
    const uint32_t aH = aHi + (uint32_t)(mt + r8) * P + g16 * 16;
    const uint32_t aL = aLo + (uint32_t)(mt + r8) * P + g16 * 16;
    const uint32_t bH = wHi + (uint32_t)r8 * P + (uint32_t)(nb + g16 * 8) * 2;
    const uint32_t bL = wLo + (uint32_t)r8 * P + (uint32_t)(nb + g16 * 8) * 2;

    #pragma unroll
    for (int kt = 0; kt < 8; kt++) {
        uint32_t ah0, ah1, ah2, ah3, al0, al1, al2, al3;
        LDSM4(ah0, ah1, ah2, ah3, aH + kt * 32);
        LDSM4(al0, al1, al2, al3, aL + kt * 32);
        #pragma unroll
        for (int np = 0; np < NNT / 2; np++) {
            uint32_t bh0, bh1, bh2, bh3, bl0, bl1, bl2, bl3;
            LDSM4T(bh0, bh1, bh2, bh3, bH + kt * 4352 + np * 32);
            LDSM4T(bl0, bl1, bl2, bl3, bL + kt * 4352 + np * 32);
            MMA16816(acc[2 * np],     ah0, ah1, ah2, ah3, bh0, bh1);
            MMA16816(acc[2 * np + 1], ah0, ah1, ah2, ah3, bh2, bh3);
            MMA16816(acc[2 * np],     ah0, ah1, ah2, ah3, bl0, bl1);
            MMA16816(acc[2 * np + 1], ah0, ah1, ah2, ah3, bl2, bl3);
            MMA16816(acc[2 * np],     al0, al1, al2, al3, bh0, bh1);
            MMA16816(acc[2 * np + 1], al0, al1, al2, al3, bh2, bh3);
        }
    }

    __syncthreads();   // all A reads done -> in-place output writes safe

    const int r0 = mt + (lane >> 2);
    #pragma unroll
    for (int t = 0; t < NNT; t++) {
        const int c0 = nb + t * 8 + (lane & 3) * 2;
        const float b0 = __ldg(bias + c0), b1 = __ldg(bias + c0 + 1);
        float av0 = 0.f, av1 = 0.f;
        if (addv) { av0 = addv[c0]; av1 = addv[c0 + 1]; }
        const float y0 = fmaxf(acc[t][0] + b0, 0.f) + av0;
        const float y1 = fmaxf(acc[t][1] + b1, 0.f) + av1;
        const float y2 = fmaxf(acc[t][2] + b0, 0.f) + av0;
        const float y3 = fmaxf(acc[t][3] + b1, 0.f) + av1;

        __nv_bfloat162 h01, h23, l01, l23;
        h01.x = __float2bfloat16(y0); h01.y = __float2bfloat16(y1);
        h23.x = __float2bfloat16(y2); h23.y = __float2bfloat16(y3);
        l01.x = __float2bfloat16(y0 - __bfloat162float(h01.x));
        l01.y = __float2bfloat16(y1 - __bfloat162float(h01.y));
        l23.x = __float2bfloat16(y2 - __bfloat162float(h23.x));
        l23.y = __float2bfloat16(y3 - __bfloat162float(h23.y));

        *(__nv_bfloat162*)(outHi + (size_t)r0 * P + c0 * 2)       = h01;
        *(__nv_bfloat162*)(outHi + (size_t)(r0 + 8) * P + c0 * 2) = h23;
        *(__nv_bfloat162*)(outLo + (size_t)r0 * P + c0 * 2)       = l01;
        *(__nv_bfloat162*)(outLo + (size_t)(r0 + 8) * P + c0 * 2) = l23;
    }
}

// ---------------- main fused kernel ----------------
__global__ __launch_bounds__(256, 1) void gnn_mma(
    const float* __restrict__ uf,   const float* __restrict__ noise,
    const float* __restrict__ b_ue,
    const float* __restrict__ W_t,  const float* __restrict__ b_t,
    const float* __restrict__ caba, const float* __restrict__ cabs,
    const float* __restrict__ cabc, const float* __restrict__ cuba,
    const float* __restrict__ cubs, const float* __restrict__ cubc,
    const float* __restrict__ Wn,   const float* __restrict__ bn,
    float* __restrict__ out)
{
    extern __shared__ __align__(16) char sm[];
    const uint32_t smb = smem_u32(sm);
    const int tid = threadIdx.x;
    const int b   = blockIdx.x;

    float* vA  = (float*)(sm + OFF_VA);
    float* vU  = (float*)(sm + OFF_VU);
    float* ant = (float*)(sm + OFF_ANT);

    // ---------- per-layer schedule ----------
    const int WIDX[19] = {0, 1,2, 7,8, 3,4, 5,6, 9,10, 11,12, 1,2, 3,4, 5,6};
    const int MROW[19] = {32, 32,32, 64,64, 64,64, 64,64, 32,32, 32,32, 32,32, 64,64, 64,64};
    const int AIN[19]  = {OFF_TC, OFF_TU,OFF_TC, OFF_TA,OFF_TC, OFF_TA,OFF_TC,
                          OFF_TC,OFF_TC, OFF_TU,OFF_TC, OFF_TC,OFF_TC,
                          OFF_TU,OFF_TC, OFF_TA,OFF_TC, OFF_TC,OFF_TC};
    const int AINL[19] = {OFF_TC_L, OFF_TU_L,OFF_TC_L, OFF_TA_L,OFF_TC_L, OFF_TA_L,OFF_TC_L,
                          OFF_TC_L,OFF_TC_L, OFF_TU_L,OFF_TC_L, OFF_TC_L,OFF_TC_L,
                          OFF_TU_L,OFF_TC_L, OFF_TA_L,OFF_TC_L, OFF_TC_L,OFF_TC_L};
    const int AOUT[19] = {OFF_TU, OFF_TC,OFF_TC, OFF_TC,OFF_TC, OFF_TC,OFF_TC,
                          OFF_TC,OFF_TA, OFF_TC,OFF_TC, OFF_TC,OFF_TU,
                          OFF_TC,OFF_TC, OFF_TC,OFF_TC, OFF_TC,OFF_TA};
    const int AOUTL[19]= {OFF_TU_L, OFF_TC_L,OFF_TC_L, OFF_TC_L,OFF_TC_L, OFF_TC_L,OFF_TC_L,
                          OFF_TC_L,OFF_TA_L, OFF_TC_L,OFF_TC_L, OFF_TC_L,OFF_TU_L,
                          OFF_TC_L,OFF_TC_L, OFF_TC_L,OFF_TC_L, OFF_TC_L,OFF_TA_L};
    const int ADDV[19] = {0, 0,0, 0,0, 0,1, 0,0, 0,2, 0,0, 0,0, 0,1, 0,0};
    const int MEAN[19] = {0, 0,1, 0,2, 0,0, 0,0, 0,0, 0,0, 0,1, 0,0, 0,0};
    const float* BIAS[19] = {
        b_ue, caba, caba + 128, cuba, cuba + 128, cabs, cabs + 128,
        cabc, cabc + 128, cubs, cubs + 128, cubc, cubc + 128,
        caba, caba + 128, cabs, cabs + 128, cabc, cabc + 128
    };

    // ---------- prefetch W0, W1 (each 69632B = 4352 x 16B; 17/thread) ----------
    {
        const char* g0 = (const char*)&g_w[WIDX[0]][0][0];
        const char* g1 = (const char*)&g_w[WIDX[1]][0][0];
        #pragma unroll
        for (int i = 0; i < 17; i++) {
            const int e = tid + i * 256;
            CP16(smb + OFF_W0 + e * 16, g0 + e * 16);
        }
        CP_COMMIT();
        #pragma unroll
        for (int i = 0; i < 17; i++) {
            const int e = tid + i * 256;
            CP16(smb + OFF_W1 + e * 16, g1 + e * 16);
        }
        CP_COMMIT();
    }

    // ---------- build encoder input tile (TC): split user_feat hi/lo ----------
    {
        const float* src = uf + (size_t)b * NU_ * HD;
        for (int idx = tid; idx < NU_ * HD; idx += 256) {
            const int m = idx >> 7, k = idx & 127;
            const float v = __ldg(src + idx);
            const __nv_bfloat16 h = __float2bfloat16(v);
            *(__nv_bfloat16*)(sm + OFF_TC   + (size_t)m * P + k * 2) = h;
            *(__nv_bfloat16*)(sm + OFF_TC_L + (size_t)m * P + k * 2) =
                __float2bfloat16(v - __bfloat162float(h));
        }
    }

    // ==================== layer loop ====================
    for (int L = 0; L < 19; L++) {
        CP_WAIT1();          // W[L] arrived (W[L+1] may still fly)
        __syncthreads();     // A tile + weights visible to all

        const uint32_t wbuf = smb + ((L & 1) ? OFF_W1 : OFF_W0);
        const float* addp = (ADDV[L] == 1) ? vA : (ADDV[L] == 2) ? vU : nullptr;

        if (MROW[L] == 64)
            do_layer<8>(smb + AIN[L], smb + AINL[L], wbuf, wbuf + WPLANE,
                        sm + AOUT[L], sm + AOUTL[L], BIAS[L], addp, tid);
        else
            do_layer<4>(smb + AIN[L], smb + AINL[L], wbuf, wbuf + WPLANE,
                        sm + AOUT[L], sm + AOUTL[L], BIAS[L], addp, tid);

        // prefetch W[L+2] into the buffer layer L just finished reading
        if (L + 2 < 19) {
            const char* g = (const char*)&g_w[WIDX[L + 2]][0][0];
            const uint32_t dst = smb + ((L & 1) ? OFF_W1 : OFF_W0);
            #pragma unroll
            for (int i = 0; i < 17; i++) {
                const int e = tid + i * 256;
                CP16(dst + e * 16, g + e * 16);
            }
        }
        CP_COMMIT();

        __syncthreads();     // epilogue writes visible

        if (MEAN[L]) {       // column mean over the nodes just produced
            if (tid < HD) {
                const int n = (MEAN[L] == 1) ? 32 : 64;
                const char* oh = sm + AOUT[L];
                const char* ol = sm + AOUTL[L];
                float s = 0.f;
                for (int m = 0; m < n; m++)
                    s += bget(oh + (size_t)m * P + tid * 2) +
                         bget(ol + (size_t)m * P + tid * 2);
                ((MEAN[L] == 1) ? vA : vU)[tid] = s / (float)n;
            }
            // consumed >=2 layers later; loop-top sync suffices
        }

        if (L == 0) {        // ant vector + ha tile init
            if (tid < HD) {  // mean of hu over 32 users
                float s = 0.f;
                for (int m = 0; m < NU_; m++)
                    s += bget(sm + OFF_TU   + (size_t)m * P + tid * 2) +
                         bget(sm + OFF_TU_L + (size_t)m * P + tid * 2);
                vA[tid] = s / (float)NU_;
            }
            __syncthreads();
            if (tid < HD) {  // ant = relu(mean @ W_t + b_t)
                float acc = __ldg(b_t + tid);
                #pragma unroll 8
                for (int k = 0; k < HD; k++)
                    acc += vA[k] * __ldg(W_t + k * HD + tid);
                ant[tid] = fmaxf(acc, 0.f);
            }
            __syncthreads();
            {                // TA = repeat(ant) + noise, split hi/lo
                const float* np_ = noise + (size_t)b * NT_ * HD;
                for (int idx = tid; idx < NT_ * HD; idx += 256) {
                    const int m = idx >> 7, f = idx & 127;
                    const float v = ant[f] + __ldg(np_ + idx);
                    const __nv_bfloat16 h = __float2bfloat16(v);
                    *(__nv_bfloat16*)(sm + OFF_TA   + (size_t)m * P + f * 2) = h;
                    *(__nv_bfloat16*)(sm + OFF_TA_L + (size_t)m * P + f * 2) =
                        __float2bfloat16(v - __bfloat162float(h));
                }
            }
        }
    }
    __syncthreads();

    // ==================== final projection + normalization ====================
    float* TAf = (float*)(sm + OFF_W0);            // [64][128] fp32 ha2
    float* WnS = (float*)(sm + OFF_W1);            // [128][16]
    float* nbuf = (float*)(sm + OFF_W1 + 8192);    // [64][16]
    for (int idx = tid; idx < NT_ * HD; idx += 256) {
        const int m = idx >> 7, k = idx & 127;
        TAf[idx] = bget(sm + OFF_TA   + (size_t)m * P + k * 2) +
                   bget(sm + OFF_TA_L + (size_t)m * P + k * 2);
    }
    for (int i = tid; i < HD * 16; i += 256) WnS[i] = __ldg(Wn + i);
    __syncthreads();

    const int c  = tid & 15;
    const int rb = tid >> 4;
    float yv[4];
    #pragma unroll
    for (int i = 0; i < 4; i++) {
        const int r = rb + 16 * i;
        float acc = __ldg(bn + c);
        #pragma unroll 8
        for (int k = 0; k < HD; k++)
            acc += TAf[r * HD + k] * WnS[k * 16 + c];
        nbuf[r * 16 + c] = acc;
        yv[i] = acc;
    }
    __syncthreads();
    #pragma unroll
    for (int i = 0; i < 4; i++) {
        const int r  = rb + 16 * i;
        const int cp = c & 7;
        const float re  = nbuf[r * 16 + cp];
        const float im  = nbuf[r * 16 + cp + 8];
        const float mag = sqrtf(re * re + im * im);
        out[((size_t)b * NT_ + r) * 16 + c] = yv[i] / mag;
    }
}

// ---------------------------------------------------------------------
extern "C" void kernel_launch(void* const* d_in, const int* in_sizes, int n_in,
                              void* d_out, int out_size)
{
    (void)in_sizes; (void)n_in; (void)out_size;

    const float* user_feat = (const float*)d_in[0];
    const float* ant_noise = (const float*)d_in[1];
    // d_in[2..5]: edge indices — deterministic full bipartite per batch; unused.
    const float* W_ue = (const float*)d_in[6];
    const float* b_ue = (const float*)d_in[7];
    const float* W_t  = (const float*)d_in[8];
    const float* b_t  = (const float*)d_in[9];
    const float* caWa = (const float*)d_in[10];
    const float* caba = (const float*)d_in[11];
    const float* caWs = (const float*)d_in[12];
    const float* cabs = (const float*)d_in[13];
    const float* caWc = (const float*)d_in[14];
    const float* cabc = (const float*)d_in[15];
    const float* cuWa = (const float*)d_in[16];
    const float* cuba = (const float*)d_in[17];
    const float* cuWs = (const float*)d_in[18];
    const float* cubs = (const float*)d_in[19];
    const float* cuWc = (const float*)d_in[20];
    const float* cubc = (const float*)d_in[21];
    const float* Wn   = (const float*)d_in[22];
    const float* bn   = (const float*)d_in[23];
    float* out = (float*)d_out;

    static int init_done = 0;
    if (!init_done) {
        cudaFuncSetAttribute(gnn_mma,
                             cudaFuncAttributeMaxDynamicSharedMemorySize,
                             SM_BYTES);
        init_done = 1;
    }

    prep_w<<<13, 256>>>(W_ue, caWa, caWs, caWc, cuWa, cuWs, cuWc);
    gnn_mma<<<B_, 256, SM_BYTES>>>(
        user_feat, ant_noise, b_ue, W_t, b_t,
        caba, cabs, cabc, cuba, cubs, cubc,
        Wn, bn, out);
}